// round 3
// baseline (speedup 1.0000x reference)
#include <cuda_runtime.h>
#include <cstdint>

namespace {

constexpr int NTH  = 256;
constexpr int NBLK = 4096;
constexpr int ROWS = 1024;

// cost chain: cn + cb.x*x.x + ... where x is pre-scaled by -2 (|x|^2 term dropped:
// it is constant across states per step, so it cannot change any argmin)
__device__ __forceinline__ float costf(const float4 cb, float cn, const float4 x) {
    return fmaf(cb.w, x.w, fmaf(cb.z, x.z, fmaf(cb.y, x.y, fmaf(cb.x, x.x, cn))));
}
__device__ __forceinline__ float cnrm(const float4 c) {
    return fmaf(c.w, c.w, fmaf(c.z, c.z, fmaf(c.y, c.y, c.x * c.x)));
}

__global__ __launch_bounds__(NTH, 6)
void viterbi_kernel(const float* __restrict__ array,
                    const float* __restrict__ codebook,
                    float* __restrict__ out,
                    int out_size)
{
    __shared__ float alpha[2][1024];          // ping-pong alpha (linear layout, conflict-free)
    __shared__ float4 xs[64];                 // -2 * x chunks
    __shared__ unsigned int bpsm[4][256];     // packed backpointers: bpsm[t>>4][g], 2 bits per step
    __shared__ int   path[64];
    __shared__ float redv[8];
    __shared__ int   redi[8];

    const int k  = threadIdx.x;               // state group: owns states 4k..4k+3
    const int b  = blockIdx.x;
    const int br = b >> 6;
    const int bc = b & 63;

    // ---- load this block's 256 elements, pre-scaled by -2 ----
    {
        int r = k >> 4, cc = k & 15;
        float v = array[(br * 16 + r) * ROWS + (bc * 16 + cc)];
        reinterpret_cast<float*>(xs)[k] = -2.0f * v;
    }

    // ---- codebook rows 4k..4k+3 in registers (fixed for all steps) ----
    const float4* cb4 = reinterpret_cast<const float4*>(codebook);
    float4 o0 = __ldg(cb4 + 4 * k + 0);
    float4 o1 = __ldg(cb4 + 4 * k + 1);
    float4 o2 = __ldg(cb4 + 4 * k + 2);
    float4 o3 = __ldg(cb4 + 4 * k + 3);
    float on0 = cnrm(o0), on1 = cnrm(o1), on2 = cnrm(o2), on3 = cnrm(o3);

    __syncthreads();

    // ---- alpha_0 = cost(x0) (free initial state) -> alpha[0] ----
    float4 x0 = xs[0];
    float v0 = costf(o0, on0, x0);
    float v1 = costf(o1, on1, x0);
    float v2 = costf(o2, on2, x0);
    float v3 = costf(o3, on3, x0);
    *reinterpret_cast<float4*>(&alpha[0][4 * k]) = make_float4(v0, v1, v2, v3);
    __syncthreads();

    // ---- forward recursion: 63 steps in 4 chunks of (15,16,16,16) ----
    // step t: read alpha[(t+1)&1], write alpha[t&1]
#pragma unroll 1
    for (int tc = 0; tc < 4; ++tc) {
        unsigned int cw = 0;                  // 2-bit backpointers for this 16-step chunk
#pragma unroll
        for (int u = 0; u < 16; ++u) {
            const int t = 16 * tc + u;        // u, parity, shifts all compile-time constants
            if (t == 0) continue;             // chunk 0 starts at t=1
            const float* ap = alpha[(t + 1) & 1];
            float a0 = ap[k];
            float a1 = ap[k + 256];
            float a2 = ap[k + 512];
            float a3 = ap[k + 768];
            // packed-mantissa argmin: 2 LSBs carry j; ordering preserved, ties impossible
            float p0 = __uint_as_float((__float_as_uint(a0) & ~3u) | 0u);
            float p1 = __uint_as_float((__float_as_uint(a1) & ~3u) | 1u);
            float p2 = __uint_as_float((__float_as_uint(a2) & ~3u) | 2u);
            float p3 = __uint_as_float((__float_as_uint(a3) & ~3u) | 3u);
            float m  = fminf(fminf(p0, p1), fminf(p2, p3));
            cw |= (__float_as_uint(m) & 3u) << (2 * u);

            float4 xt = xs[t];
            v0 = m + costf(o0, on0, xt);
            v1 = m + costf(o1, on1, xt);
            v2 = m + costf(o2, on2, xt);
            v3 = m + costf(o3, on3, xt);
            *reinterpret_cast<float4*>(&alpha[t & 1][4 * k]) = make_float4(v0, v1, v2, v3);

            if (u == 15) bpsm[tc][k] = cw;    // flush chunk's backpointers once
            __syncthreads();
        }
    }

    // ---- final argmin over 1024 states (first-occurrence semantics) ----
    float bm = v0; int bi = 4 * k;
    if (v1 < bm) { bm = v1; bi = 4 * k + 1; }
    if (v2 < bm) { bm = v2; bi = 4 * k + 2; }
    if (v3 < bm) { bm = v3; bi = 4 * k + 3; }
#pragma unroll
    for (int off = 16; off; off >>= 1) {
        float om = __shfl_down_sync(0xffffffffu, bm, off);
        int   oi = __shfl_down_sync(0xffffffffu, bi, off);
        if (om < bm || (om == bm && oi < bi)) { bm = om; bi = oi; }
    }
    if ((k & 31) == 0) { redv[k >> 5] = bm; redi[k >> 5] = bi; }
    __syncthreads();

    // ---- backtrack (single thread; hidden by co-resident CTAs) ----
    if (k == 0) {
        float m = redv[0]; int s = redi[0];
#pragma unroll
        for (int w = 1; w < 8; ++w) {
            if (redv[w] < m || (redv[w] == m && redi[w] < s)) { m = redv[w]; s = redi[w]; }
        }
        path[63] = s;
        for (int t = 63; t >= 1; --t) {
            int g = s >> 2;
            int j = (bpsm[t >> 4][g] >> (2 * (t & 15))) & 3;
            s = g + (j << 8);                 // prev = (s>>2) + j*HI, HI = 256
            path[t - 1] = s;
        }
    }
    __syncthreads();

    // ---- emit: rec (exact codebook gather) + states ----
    if (k < 64) {
        int t = k;
        int s = path[t];
        float4 val = __ldg(cb4 + s);
        int row = br * 16 + (t >> 2);
        int col = bc * 16 + ((t & 3) << 2);
        reinterpret_cast<float4*>(out + row * ROWS + col)[0] = val;
        int sidx = ROWS * ROWS + b * 64 + t;
        if (sidx < out_size) out[sidx] = (float)s;
    }
}

} // namespace

extern "C" void kernel_launch(void* const* d_in, const int* in_sizes, int n_in,
                              void* d_out, int out_size) {
    const float* array    = (const float*)d_in[0];
    const float* codebook = (const float*)d_in[1];
    (void)in_sizes; (void)n_in;
    float* out = (float*)d_out;
    viterbi_kernel<<<NBLK, NTH>>>(array, codebook, out, out_size);
}

// round 4
// speedup vs baseline: 1.0528x; 1.0528x over previous
#include <cuda_runtime.h>
#include <cstdint>

namespace {

constexpr int NTH  = 256;
constexpr int NBLK = 4096;
constexpr int ROWS = 1024;

typedef unsigned long long u64;

// packed f32x2 helpers (sm_103a; PTX-only, ptxas never auto-fuses)
__device__ __forceinline__ u64 pk2(float lo, float hi) {
    u64 d; asm("mov.b64 %0, {%1, %2};" : "=l"(d) : "f"(lo), "f"(hi)); return d;
}
__device__ __forceinline__ void upk2(float& lo, float& hi, u64 p) {
    asm("mov.b64 {%0, %1}, %2;" : "=f"(lo), "=f"(hi) : "l"(p));
}
__device__ __forceinline__ u64 fma2(u64 a, u64 b, u64 c) {
    u64 d; asm("fma.rn.f32x2 %0, %1, %2, %3;" : "=l"(d) : "l"(a), "l"(b), "l"(c)); return d;
}
__device__ __forceinline__ u64 add2(u64 a, u64 b) {
    u64 d; asm("add.rn.f32x2 %0, %1, %2;" : "=l"(d) : "l"(a), "l"(b)); return d;
}

__device__ __forceinline__ float cnrm(const float4 c) {
    return fmaf(c.w, c.w, fmaf(c.z, c.z, fmaf(c.y, c.y, c.x * c.x)));
}

__global__ __launch_bounds__(NTH, 6)
void viterbi_kernel(const float* __restrict__ array,
                    const float* __restrict__ codebook,
                    float* __restrict__ out,
                    int out_size)
{
    __shared__ float alpha[2][1024];             // ping-pong alpha
    __shared__ u64 xsd[64][4];                   // -2*x, each component duplicated as a pair
    __shared__ unsigned char bpSh[64][NTH];      // 2-bit j per state-group per step
    __shared__ int   path[64];
    __shared__ float redv[8];
    __shared__ int   redi[8];

    const int k  = threadIdx.x;                  // state group: owns states 4k..4k+3
    const int b  = blockIdx.x;
    const int br = b >> 6;
    const int bc = b & 63;

    // ---- load this block's 256 elements, pre-scaled by -2, duplicated pairs ----
    {
        int r = k >> 4, cc = k & 15;
        float v = -2.0f * array[(br * 16 + r) * ROWS + (bc * 16 + cc)];
        // element index e = k: t = e>>2, component = e&3
        xsd[k >> 2][k & 3] = pk2(v, v);
    }

    // ---- codebook rows 4k..4k+3 -> packed pair registers ----
    const float4* cb4 = reinterpret_cast<const float4*>(codebook);
    float4 o0 = __ldg(cb4 + 4 * k + 0);
    float4 o1 = __ldg(cb4 + 4 * k + 1);
    float4 o2 = __ldg(cb4 + 4 * k + 2);
    float4 o3 = __ldg(cb4 + 4 * k + 3);
    // pair (even state, odd state) per chunk component
    u64 cx01 = pk2(o0.x, o1.x), cy01 = pk2(o0.y, o1.y), cz01 = pk2(o0.z, o1.z), cw01 = pk2(o0.w, o1.w);
    u64 cx23 = pk2(o2.x, o3.x), cy23 = pk2(o2.y, o3.y), cz23 = pk2(o2.z, o3.z), cw23 = pk2(o2.w, o3.w);
    u64 cn01 = pk2(cnrm(o0), cnrm(o1));
    u64 cn23 = pk2(cnrm(o2), cnrm(o3));

    __syncthreads();

    // ---- alpha_0 = cost(x0) (free initial state) -> alpha[0] ----
    u64 v01, v23;
    {
        const u64* xq = xsd[0];
        u64 xx = xq[0], xy = xq[1], xz = xq[2], xw = xq[3];
        v01 = fma2(cw01, xw, fma2(cz01, xz, fma2(cy01, xy, fma2(cx01, xx, cn01))));
        v23 = fma2(cw23, xw, fma2(cz23, xz, fma2(cy23, xy, fma2(cx23, xx, cn23))));
        ulonglong2* dst = reinterpret_cast<ulonglong2*>(&alpha[0][4 * k]);
        *dst = make_ulonglong2(v01, v23);
    }
    __syncthreads();

    // ---- forward recursion: 63 steps (identical structure to best-measured R1) ----
#pragma unroll 2
    for (int t = 1; t < 64; ++t) {
        const float* ap = alpha[(t + 1) & 1];
        float a0 = ap[k];
        float a1 = ap[k + 256];
        float a2 = ap[k + 512];
        float a3 = ap[k + 768];
        float m = a0; int j = 0;                 // strict < -> first-occurrence argmin
        if (a1 < m) { m = a1; j = 1; }
        if (a2 < m) { m = a2; j = 2; }
        if (a3 < m) { m = a3; j = 3; }
        bpSh[t][k] = (unsigned char)j;

        const u64* xq = xsd[t];
        u64 xx = xq[0], xy = xq[1], xz = xq[2], xw = xq[3];
        u64 mm = pk2(m, m);
        // v = m + (cn + cb.x + ...) : same fmaf chain per lane as scalar version
        u64 c01 = fma2(cw01, xw, fma2(cz01, xz, fma2(cy01, xy, fma2(cx01, xx, cn01))));
        u64 c23 = fma2(cw23, xw, fma2(cz23, xz, fma2(cy23, xy, fma2(cx23, xx, cn23))));
        v01 = add2(mm, c01);
        v23 = add2(mm, c23);
        ulonglong2* dst = reinterpret_cast<ulonglong2*>(&alpha[t & 1][4 * k]);
        *dst = make_ulonglong2(v01, v23);
        __syncthreads();
    }

    // ---- final argmin over 1024 states (first-occurrence semantics) ----
    float v0, v1, v2, v3;
    upk2(v0, v1, v01);
    upk2(v2, v3, v23);
    float bm = v0; int bi = 4 * k;
    if (v1 < bm) { bm = v1; bi = 4 * k + 1; }
    if (v2 < bm) { bm = v2; bi = 4 * k + 2; }
    if (v3 < bm) { bm = v3; bi = 4 * k + 3; }
#pragma unroll
    for (int off = 16; off; off >>= 1) {
        float om = __shfl_down_sync(0xffffffffu, bm, off);
        int   oi = __shfl_down_sync(0xffffffffu, bi, off);
        if (om < bm || (om == bm && oi < bi)) { bm = om; bi = oi; }
    }
    if ((k & 31) == 0) { redv[k >> 5] = bm; redi[k >> 5] = bi; }
    __syncthreads();

    // ---- backtrack (single thread; hidden by co-resident CTAs) ----
    if (k == 0) {
        float m = redv[0]; int s = redi[0];
#pragma unroll
        for (int w = 1; w < 8; ++w) {
            if (redv[w] < m || (redv[w] == m && redi[w] < s)) { m = redv[w]; s = redi[w]; }
        }
        path[63] = s;
        for (int t = 63; t >= 1; --t) {
            int g = s >> 2;
            int j = bpSh[t][g];
            s = g + (j << 8);                    // prev = (s>>2) + j*HI, HI = 256
            path[t - 1] = s;
        }
    }
    __syncthreads();

    // ---- emit: rec (exact codebook gather) + states ----
    if (k < 64) {
        int t = k;
        int s = path[t];
        float4 val = __ldg(cb4 + s);
        int row = br * 16 + (t >> 2);
        int col = bc * 16 + ((t & 3) << 2);
        reinterpret_cast<float4*>(out + row * ROWS + col)[0] = val;
        int sidx = ROWS * ROWS + b * 64 + t;
        if (sidx < out_size) out[sidx] = (float)s;
    }
}

} // namespace

extern "C" void kernel_launch(void* const* d_in, const int* in_sizes, int n_in,
                              void* d_out, int out_size) {
    const float* array    = (const float*)d_in[0];
    const float* codebook = (const float*)d_in[1];
    (void)in_sizes; (void)n_in;
    float* out = (float*)d_out;
    viterbi_kernel<<<NBLK, NTH>>>(array, codebook, out, out_size);
}